// round 14
// baseline (speedup 1.0000x reference)
#include <cuda_runtime.h>
#include <cuda_bf16.h>

#define N 4096
#define THREADS 256
#define PPB 4                      /* pedestrians per block */
#define NBLOCKS (N / PPB)          /* 1024 */
#define ITERS 16                   /* per warp: 16 iters x 2 candidates/lane */
#define BUFCAP 32

typedef unsigned long long ull;
#define FULL 0xffffffffu
#define INFBITS 0x7f800000u

__device__ __forceinline__ ull pack2(float lo, float hi) {
    ull r;
    asm("mov.b64 %0, {%1, %2};" : "=l"(r) : "f"(lo), "f"(hi));
    return r;
}
__device__ __forceinline__ void unpack2(ull v, float& lo, float& hi) {
    asm("mov.b64 {%0, %1}, %2;" : "=f"(lo), "=f"(hi) : "l"(v));
}
__device__ __forceinline__ ull add2(ull a, ull b) {
    ull r;
    asm("add.rn.f32x2 %0, %1, %2;" : "=l"(r) : "l"(a), "l"(b));
    return r;
}
__device__ __forceinline__ ull fma2(ull a, ull b, ull c) {
    ull r;
    asm("fma.rn.f32x2 %0, %1, %2, %3;" : "=l"(r) : "l"(a), "l"(b), "l"(c));
    return r;
}

// dd = (dx*dx + 1) + dy*dy for one candidate; pair (x,y) is register-adjacent.
__device__ __forceinline__ float dist1(ull pxy, ull npi, ull onz) {
    ull d = add2(pxy, npi);          // (dx, dy)
    ull s = fma2(d, d, onz);         // (dx^2+1, dy^2)
    float sx, sy; unpack2(s, sx, sy);
    return sx + sy;
}

__global__ __launch_bounds__(THREADS, 7)   /* <=36 regs -> 7 blocks/SM -> ONE wave */
void nn_tag_pool_kernel(const float* __restrict__ obs1,
                        const float* __restrict__ obs2,
                        const float* __restrict__ W,
                        const float* __restrict__ b,
                        float* __restrict__ out)
{
    __shared__ unsigned s_cnt[PPB];
    __shared__ unsigned s_vth[PPB];     // positive-float bits: uint order == float order
    __shared__ ull s_buf[PPB][BUFCAP];

    const int lane = threadIdx.x & 31;
    const int warp = threadIdx.x >> 5;
    const int pair    = warp >> 2;       // 0..1 : which ped-pair of this block
    const int quarter = warp & 3;        // 0..3 : which candidate quarter
    const int i0 = blockIdx.x * PPB + pair * 2;
    const int i1 = i0 + 1;

    if (threadIdx.x < PPB) { s_cnt[threadIdx.x] = 0; s_vth[threadIdx.x] = INFBITS; }
    __syncthreads();

    const float2* __restrict__ pos2 = (const float2*)obs2;
    const float4* __restrict__ pos4 = (const float4*)obs2;
    const float2 pa = __ldg(&pos2[i0]);
    const float2 pb = __ldg(&pos2[i1]);

    const ull onz = pack2(1.0f, 0.0f);
    const ull npA = pack2(-pa.x, -pa.y);
    const ull npB = pack2(-pb.x, -pb.y);

    const float INF = __int_as_float(INFBITS);
    float a0 = INF, a1 = INF;   // ped A per-lane top-2 (self included, dd==1.0 min)
    float b0 = INF, b1 = INF;   // ped B

    const int base4 = quarter * 512 + lane;   // float4 index: 512 per quarter

    // ---- Phase 1: direct-gmem packed scan; exact per-lane keep-2 over 32 cands.
    // unroll 4 (not 8): cap front-batched LDGs -> lower cross-CTA L1tex spread.
    #pragma unroll 4
    for (int t = 0; t < ITERS; t++) {
        const float4 p = __ldg(&pos4[base4 + t * 32]);
        const ull c0 = pack2(p.x, p.y);   // adjacent: free
        const ull c1 = pack2(p.z, p.w);
        {   float ta = dist1(c0, npA, onz);
            float tb = dist1(c1, npA, onz);
            float lo = fminf(ta, tb), hi = fmaxf(ta, tb);
            float m = fmaxf(a0, lo);
            a0 = fminf(a0, lo);
            a1 = fminf(fminf(a1, hi), m); }
        {   float ta = dist1(c0, npB, onz);
            float tb = dist1(c1, npB, onz);
            float lo = fminf(ta, tb), hi = fmaxf(ta, tb);
            float m = fmaxf(b0, lo);
            b0 = fminf(b0, lo);
            b1 = fminf(fminf(b1, hi), m); }
    }

    // ---- Phase 2: retained-5th for A and B, interleaved for latency overlap.
    // vth >= global 5th-smallest (incl. self): exhaustive filter for top-4 + self.
    {
        unsigned eA0 = __float_as_uint(a0), eA1 = __float_as_uint(a1);
        unsigned eB0 = __float_as_uint(b0), eB1 = __float_as_uint(b1);
        unsigned mA = INFBITS, mB = INFBITS;
        #pragma unroll
        for (int r = 0; r < 5; r++) {
            mA = __reduce_min_sync(FULL, eA0);
            mB = __reduce_min_sync(FULL, eB0);
            unsigned balA = __ballot_sync(FULL, eA0 == mA);
            unsigned balB = __ballot_sync(FULL, eB0 == mB);
            if (lane == __ffs(balA) - 1) { eA0 = eA1; eA1 = INFBITS; }
            if (lane == __ffs(balB) - 1) { eB0 = eB1; eB1 = INFBITS; }
        }
        if (lane == 0) {
            atomicMin(&s_vth[pair * 2 + 0], mA);
            atomicMin(&s_vth[pair * 2 + 1], mB);
        }
    }
    __syncthreads();
    const float vthA = __uint_as_float(s_vth[pair * 2 + 0]);
    const float vthB = __uint_as_float(s_vth[pair * 2 + 1]);
    const float vmax = fmaxf(vthA, vthB);

    // ---- Phase 3: rescan (L1-hot); vote-gated rare append of (distbits, idx).
    #pragma unroll 4
    for (int t = 0; t < ITERS; t++) {
        const float4 p = __ldg(&pos4[base4 + t * 32]);
        const ull c0 = pack2(p.x, p.y);
        const ull c1 = pack2(p.z, p.w);
        float tA0 = dist1(c0, npA, onz);
        float tA1 = dist1(c1, npA, onz);
        float tB0 = dist1(c0, npB, onz);
        float tB1 = dist1(c1, npB, onz);
        float gm = fminf(fminf(tA0, tA1), fminf(tB0, tB1));
        if (__any_sync(FULL, gm <= vmax)) {      // warp-uniform, rare
            const unsigned j0 = (unsigned)((base4 + t * 32) * 2);
            if (tA0 <= vthA) {
                unsigned s = atomicAdd(&s_cnt[pair * 2 + 0], 1u);
                if (s < BUFCAP) s_buf[pair * 2 + 0][s] = (((ull)__float_as_uint(tA0)) << 32) | j0;
            }
            if (tA1 <= vthA) {
                unsigned s = atomicAdd(&s_cnt[pair * 2 + 0], 1u);
                if (s < BUFCAP) s_buf[pair * 2 + 0][s] = (((ull)__float_as_uint(tA1)) << 32) | (j0 + 1);
            }
            if (tB0 <= vthB) {
                unsigned s = atomicAdd(&s_cnt[pair * 2 + 1], 1u);
                if (s < BUFCAP) s_buf[pair * 2 + 1][s] = (((ull)__float_as_uint(tB0)) << 32) | j0;
            }
            if (tB1 <= vthB) {
                unsigned s = atomicAdd(&s_cnt[pair * 2 + 1], 1u);
                if (s < BUFCAP) s_buf[pair * 2 + 1][s] = (((ull)__float_as_uint(tB1)) << 32) | (j0 + 1);
            }
        }
    }
    __syncthreads();

    // ---- Phase 4 + epilogue: warps 0..3 each finish one pedestrian.
    if (warp < PPB) {
        const int ip = blockIdx.x * PPB + warp;
        unsigned n = s_cnt[warp]; if (n > BUFCAP) n = BUFCAP;
        unsigned db = FULL, ji = FULL;
        if ((unsigned)lane < n) {
            ull k = s_buf[warp][lane];
            db = (unsigned)(k >> 32);
            ji = (unsigned)k;
        }
        // exclude self: its distance is bit-exactly 1.0f
        if (db == 0x3f800000u && ji == (unsigned)ip) db = FULL;

        const int kk = lane >> 3;   // neighbor rank for this lane
        const int o  = lane & 7;    // output channel for this lane
        unsigned nb = 0;
        #pragma unroll
        for (int r = 0; r < 4; r++) {
            unsigned md = __reduce_min_sync(FULL, db);
            unsigned ci = (db == md) ? ji : FULL;
            unsigned mi = __reduce_min_sync(FULL, ci);   // lower-index tie-break
            if (kk == r) nb = mi;
            if (db == md && ji == mi) db = FULL;         // pop exactly one entry
        }
        nb &= (N - 1);   // memory safety (only reachable on overflow)

        const float2* __restrict__ o1 = (const float2*)obs1;
        const float2 pp = __ldg(&pos2[ip]);
        const float2 pn = __ldg(&pos2[nb]);
        const float2 qi = __ldg(&o1[ip]);
        const float2 qn = __ldg(&o1[nb]);
        const float px = pn.x - pp.x;
        const float py = pn.y - pp.y;
        const float vx = (pn.x - qn.x) - (pp.x - qi.x);
        const float vy = (pn.y - qn.y) - (pp.y - qi.y);

        const float w0 = __ldg(&W[o * 6 + 0]);
        const float w1 = __ldg(&W[o * 6 + 1]);
        const float w2 = __ldg(&W[o * 6 + 2]);
        const float w3 = __ldg(&W[o * 6 + 3]);
        const float w4 = __ldg(&W[o * 6 + 4]);
        const float w5 = __ldg(&W[o * 6 + 5]);

        float e = __ldg(&b[o]) + w2 + w5 + w0 * px + w1 * py + w3 * vx + w4 * vy;
        out[ip * 32 + lane] = fmaxf(e, 0.0f);   // coalesced 128B store per warp
    }
}

extern "C" void kernel_launch(void* const* d_in, const int* in_sizes, int n_in,
                              void* d_out, int out_size)
{
    const float* obs1 = (const float*)d_in[0];
    const float* obs2 = (const float*)d_in[1];
    const float* W    = (const float*)d_in[2];
    const float* b    = (const float*)d_in[3];
    float* out = (float*)d_out;

    nn_tag_pool_kernel<<<NBLOCKS, THREADS>>>(obs1, obs2, W, b, out);
}

// round 15
// speedup vs baseline: 1.5739x; 1.5739x over previous
#include <cuda_runtime.h>
#include <cuda_bf16.h>

#define N 4096
#define THREADS 256
#define PPB 4                      /* pedestrians per block */
#define NBLOCKS (N / PPB)          /* 1024 */
#define ITERS 16                   /* per warp: 16 iters x 2 candidates/lane */
#define GROUPS 4                   /* phase-3 gate granularity: 4 iters = 128 cands */
#define BUFCAP 32

typedef unsigned long long ull;
#define FULL 0xffffffffu
#define INFBITS 0x7f800000u

__device__ __forceinline__ ull pack2(float lo, float hi) {
    ull r;
    asm("mov.b64 %0, {%1, %2};" : "=l"(r) : "f"(lo), "f"(hi));
    return r;
}
__device__ __forceinline__ void unpack2(ull v, float& lo, float& hi) {
    asm("mov.b64 {%0, %1}, %2;" : "=f"(lo), "=f"(hi) : "l"(v));
}
__device__ __forceinline__ ull add2(ull a, ull b) {
    ull r;
    asm("add.rn.f32x2 %0, %1, %2;" : "=l"(r) : "l"(a), "l"(b));
    return r;
}
__device__ __forceinline__ ull fma2(ull a, ull b, ull c) {
    ull r;
    asm("fma.rn.f32x2 %0, %1, %2, %3;" : "=l"(r) : "l"(a), "l"(b), "l"(c));
    return r;
}

// dd = (dx*dx + 1) + dy*dy for one candidate; pair (x,y) is register-adjacent.
__device__ __forceinline__ float dist1(ull pxy, ull npi, ull onz) {
    ull d = add2(pxy, npi);          // (dx, dy)
    ull s = fma2(d, d, onz);         // (dx^2+1, dy^2)
    float sx, sy; unpack2(s, sx, sy);
    return sx + sy;
}

__global__ __launch_bounds__(THREADS)      /* no reg cap: R14 showed squeezing regresses */
void nn_tag_pool_kernel(const float* __restrict__ obs1,
                        const float* __restrict__ obs2,
                        const float* __restrict__ W,
                        const float* __restrict__ b,
                        float* __restrict__ out)
{
    __shared__ unsigned s_cnt[PPB];
    __shared__ unsigned s_vth[PPB];     // positive-float bits: uint order == float order
    __shared__ ull s_buf[PPB][BUFCAP];

    const int lane = threadIdx.x & 31;
    const int warp = threadIdx.x >> 5;
    const int pair    = warp >> 2;       // 0..1 : which ped-pair of this block
    const int quarter = warp & 3;        // 0..3 : which candidate quarter
    const int i0 = blockIdx.x * PPB + pair * 2;
    const int i1 = i0 + 1;

    if (threadIdx.x < PPB) { s_cnt[threadIdx.x] = 0; s_vth[threadIdx.x] = INFBITS; }
    __syncthreads();

    const float2* __restrict__ pos2 = (const float2*)obs2;
    const float4* __restrict__ pos4 = (const float4*)obs2;
    const float2 pa = __ldg(&pos2[i0]);
    const float2 pb = __ldg(&pos2[i1]);

    const ull onz = pack2(1.0f, 0.0f);
    const ull npA = pack2(-pa.x, -pa.y);
    const ull npB = pack2(-pb.x, -pb.y);

    const float INF = __int_as_float(INFBITS);
    float a0 = INF, a1 = INF;   // ped A per-lane top-2 (self included, dd==1.0 min)
    float b0 = INF, b1 = INF;   // ped B
    float gm[GROUPS] = {INF, INF, INF, INF};   // per-lane group minima (A and B jointly)

    const int base4 = quarter * 512 + lane;   // float4 index: 512 per quarter

    // ---- Phase 1: direct-gmem packed scan; exact per-lane keep-2 over 32 cands.
    // Also records each 4-iter group's min distance (over both peds) for gating.
    #pragma unroll 8
    for (int t = 0; t < ITERS; t++) {
        const float4 p = __ldg(&pos4[base4 + t * 32]);
        const ull c0 = pack2(p.x, p.y);   // adjacent: free
        const ull c1 = pack2(p.z, p.w);
        float loA, loB;
        {   float ta = dist1(c0, npA, onz);
            float tb = dist1(c1, npA, onz);
            float lo = fminf(ta, tb), hi = fmaxf(ta, tb);
            float m = fmaxf(a0, lo);
            a0 = fminf(a0, lo);
            a1 = fminf(fminf(a1, hi), m);
            loA = lo; }
        {   float ta = dist1(c0, npB, onz);
            float tb = dist1(c1, npB, onz);
            float lo = fminf(ta, tb), hi = fmaxf(ta, tb);
            float m = fmaxf(b0, lo);
            b0 = fminf(b0, lo);
            b1 = fminf(fminf(b1, hi), m);
            loB = lo; }
        gm[t >> 2] = fminf(gm[t >> 2], fminf(loA, loB));
    }

    // ---- Phase 2: retained-5th for A and B, interleaved for latency overlap.
    // vth >= global 5th-smallest (incl. self): exhaustive filter for top-4 + self.
    {
        unsigned eA0 = __float_as_uint(a0), eA1 = __float_as_uint(a1);
        unsigned eB0 = __float_as_uint(b0), eB1 = __float_as_uint(b1);
        unsigned mA = INFBITS, mB = INFBITS;
        #pragma unroll
        for (int r = 0; r < 5; r++) {
            mA = __reduce_min_sync(FULL, eA0);
            mB = __reduce_min_sync(FULL, eB0);
            unsigned balA = __ballot_sync(FULL, eA0 == mA);
            unsigned balB = __ballot_sync(FULL, eB0 == mB);
            if (lane == __ffs(balA) - 1) { eA0 = eA1; eA1 = INFBITS; }
            if (lane == __ffs(balB) - 1) { eB0 = eB1; eB1 = INFBITS; }
        }
        if (lane == 0) {
            atomicMin(&s_vth[pair * 2 + 0], mA);
            atomicMin(&s_vth[pair * 2 + 1], mB);
        }
    }
    __syncthreads();
    const float vthA = __uint_as_float(s_vth[pair * 2 + 0]);
    const float vthB = __uint_as_float(s_vth[pair * 2 + 1]);
    const float vmax = fmaxf(vthA, vthB);

    // ---- Phase 3: group-gated rescan. A 128-candidate group is recomputed only
    // if some lane's phase-1 group-min admits a candidate (bit-identical math ->
    // the gate is exact; no admissible candidate can hide in a skipped group).
    #pragma unroll
    for (int g = 0; g < GROUPS; g++) {
        if (__any_sync(FULL, gm[g] <= vmax)) {       // rare, warp-uniform
            #pragma unroll
            for (int tt = 0; tt < 4; tt++) {
                const int t = g * 4 + tt;
                const float4 p = __ldg(&pos4[base4 + t * 32]);
                const ull c0 = pack2(p.x, p.y);
                const ull c1 = pack2(p.z, p.w);
                float tA0 = dist1(c0, npA, onz);
                float tA1 = dist1(c1, npA, onz);
                float tB0 = dist1(c0, npB, onz);
                float tB1 = dist1(c1, npB, onz);
                float g2 = fminf(fminf(tA0, tA1), fminf(tB0, tB1));
                if (__any_sync(FULL, g2 <= vmax)) {  // second-level gate per iter
                    const unsigned j0 = (unsigned)((base4 + t * 32) * 2);
                    if (tA0 <= vthA) {
                        unsigned s = atomicAdd(&s_cnt[pair * 2 + 0], 1u);
                        if (s < BUFCAP) s_buf[pair * 2 + 0][s] = (((ull)__float_as_uint(tA0)) << 32) | j0;
                    }
                    if (tA1 <= vthA) {
                        unsigned s = atomicAdd(&s_cnt[pair * 2 + 0], 1u);
                        if (s < BUFCAP) s_buf[pair * 2 + 0][s] = (((ull)__float_as_uint(tA1)) << 32) | (j0 + 1);
                    }
                    if (tB0 <= vthB) {
                        unsigned s = atomicAdd(&s_cnt[pair * 2 + 1], 1u);
                        if (s < BUFCAP) s_buf[pair * 2 + 1][s] = (((ull)__float_as_uint(tB0)) << 32) | j0;
                    }
                    if (tB1 <= vthB) {
                        unsigned s = atomicAdd(&s_cnt[pair * 2 + 1], 1u);
                        if (s < BUFCAP) s_buf[pair * 2 + 1][s] = (((ull)__float_as_uint(tB1)) << 32) | (j0 + 1);
                    }
                }
            }
        }
    }
    __syncthreads();

    // ---- Phase 4 + epilogue: warps 0..3 each finish one pedestrian.
    if (warp < PPB) {
        const int ip = blockIdx.x * PPB + warp;
        unsigned n = s_cnt[warp]; if (n > BUFCAP) n = BUFCAP;
        unsigned db = FULL, ji = FULL;
        if ((unsigned)lane < n) {
            ull k = s_buf[warp][lane];
            db = (unsigned)(k >> 32);
            ji = (unsigned)k;
        }
        // exclude self: its distance is bit-exactly 1.0f
        if (db == 0x3f800000u && ji == (unsigned)ip) db = FULL;

        const int kk = lane >> 3;   // neighbor rank for this lane
        const int o  = lane & 7;    // output channel for this lane
        unsigned nb = 0;
        #pragma unroll
        for (int r = 0; r < 4; r++) {
            unsigned md = __reduce_min_sync(FULL, db);
            unsigned ci = (db == md) ? ji : FULL;
            unsigned mi = __reduce_min_sync(FULL, ci);   // lower-index tie-break
            if (kk == r) nb = mi;
            if (db == md && ji == mi) db = FULL;         // pop exactly one entry
        }
        nb &= (N - 1);   // memory safety (only reachable on overflow)

        const float2* __restrict__ o1 = (const float2*)obs1;
        const float2 pp = __ldg(&pos2[ip]);
        const float2 pn = __ldg(&pos2[nb]);
        const float2 qi = __ldg(&o1[ip]);
        const float2 qn = __ldg(&o1[nb]);
        const float px = pn.x - pp.x;
        const float py = pn.y - pp.y;
        const float vx = (pn.x - qn.x) - (pp.x - qi.x);
        const float vy = (pn.y - qn.y) - (pp.y - qi.y);

        const float w0 = __ldg(&W[o * 6 + 0]);
        const float w1 = __ldg(&W[o * 6 + 1]);
        const float w2 = __ldg(&W[o * 6 + 2]);
        const float w3 = __ldg(&W[o * 6 + 3]);
        const float w4 = __ldg(&W[o * 6 + 4]);
        const float w5 = __ldg(&W[o * 6 + 5]);

        float e = __ldg(&b[o]) + w2 + w5 + w0 * px + w1 * py + w3 * vx + w4 * vy;
        out[ip * 32 + lane] = fmaxf(e, 0.0f);   // coalesced 128B store per warp
    }
}

extern "C" void kernel_launch(void* const* d_in, const int* in_sizes, int n_in,
                              void* d_out, int out_size)
{
    const float* obs1 = (const float*)d_in[0];
    const float* obs2 = (const float*)d_in[1];
    const float* W    = (const float*)d_in[2];
    const float* b    = (const float*)d_in[3];
    float* out = (float*)d_out;

    nn_tag_pool_kernel<<<NBLOCKS, THREADS>>>(obs1, obs2, W, b, out);
}